// round 9
// baseline (speedup 1.0000x reference)
#include <cuda_runtime.h>

#define M_DIM 1024
#define E_DIM 64
#define S_DIM 2048
#define GS_TOK 8192
#define GEMM_BLOCKS 128      // 64 tokens per block
#define FILL_BLOCKS 2048
#define TOTAL_BLOCKS (GEMM_BLOCKS + 1 + FILL_BLOCKS)   // coordinator = bid 128

__device__ float g_proxy_partial[GEMM_BLOCKS * E_DIM];
__device__ int   g_expert[GS_TOK];
__device__ float g_gate[GS_TOK];
__device__ int   g_epos[GS_TOK];     // e*C+pos if kept, -1 if dropped
__device__ float g_aux;
__device__ unsigned int g_gemm_done;

// ---------------------------------------------------------------------------
// K1: GEMM (f32x2 FFMA) + hidden coordinator (scan+aux) + v8 zero-fill
// ---------------------------------------------------------------------------
__global__ __launch_bounds__(256)
void k1_gemm_fill(const float* __restrict__ X, const float* __restrict__ W,
                  float* __restrict__ out, long long out_size,
                  int C, float aux_scale)
{
    __shared__ union {
        struct { float As[2112]; float Bs[2048]; float proxy[E_DIM]; } g;  // L[64][65] overlays As
        struct { int hist[64 * E_DIM]; unsigned char rank8[S_DIM]; unsigned char ex8[S_DIM];
                 float red[E_DIM]; } s;
    } sm;

    int b = blockIdx.x;
    int tid = threadIdx.x;

    if (b < GEMM_BLOCKS) {
        // -------- GEMM: 64 tokens x 64 experts --------
        float* As = sm.g.As;
        float* Bs = sm.g.Bs;
        int tx = tid & 15, ty = tid >> 4;
        if (tid < E_DIM) sm.g.proxy[tid] = 0.f;

        unsigned long long acc2[4][2];
        #pragma unroll
        for (int i = 0; i < 4; i++) { acc2[i][0] = 0ull; acc2[i][1] = 0ull; }

        int tbase = b * 64;
        const float* Xb = X + (long long)tbase * M_DIM;

        for (int kt = 0; kt < M_DIM; kt += 32) {
            #pragma unroll
            for (int j = 0; j < 2; j++) {
                int t  = (tid >> 3) + j * 32;
                int kq = tid & 7;
                float4 v = *(const float4*)(Xb + (long long)t * M_DIM + kt + kq * 4);
                float* dst = As + t * 33 + kq * 4;
                dst[0] = v.x; dst[1] = v.y; dst[2] = v.z; dst[3] = v.w;
            }
            #pragma unroll
            for (int j = 0; j < 2; j++) {
                int idx = tid + j * 256;
                int r = idx >> 4, c4 = idx & 15;
                ((float4*)Bs)[r * 16 + c4] = ((const float4*)(W + (long long)(kt + r) * E_DIM))[c4];
            }
            __syncthreads();
            #pragma unroll
            for (int kk = 0; kk < 32; kk++) {
                ulonglong2 bq = *((const ulonglong2*)(Bs + kk * 64) + tx);
                #pragma unroll
                for (int i = 0; i < 4; i++) {
                    float a = As[(ty * 4 + i) * 33 + kk];
                    unsigned long long ap;
                    asm("mov.b64 %0, {%1, %1};" : "=l"(ap) : "f"(a));
                    asm("fma.rn.f32x2 %0, %1, %2, %0;" : "+l"(acc2[i][0]) : "l"(ap), "l"(bq.x));
                    asm("fma.rn.f32x2 %0, %1, %2, %0;" : "+l"(acc2[i][1]) : "l"(ap), "l"(bq.y));
                }
            }
            __syncthreads();
        }

        float* L = sm.g.As;   // [64][65]
        #pragma unroll
        for (int i = 0; i < 4; i++) {
            float2 v0 = *reinterpret_cast<float2*>(&acc2[i][0]);
            float2 v1 = *reinterpret_cast<float2*>(&acc2[i][1]);
            float* row = L + (ty * 4 + i) * 65 + tx * 4;
            row[0] = v0.x; row[1] = v0.y; row[2] = v1.x; row[3] = v1.y;
        }
        __syncthreads();

        int w = tid >> 5, lane = tid & 31;
        float p0 = 0.f, p1 = 0.f;
        #pragma unroll
        for (int i = 0; i < 8; i++) {
            int row = w * 8 + i;
            float L0 = L[row * 65 + lane];
            float L1 = L[row * 65 + lane + 32];
            float v; int idx;
            if (L0 >= L1) { v = L0; idx = lane; } else { v = L1; idx = lane + 32; }
            #pragma unroll
            for (int off = 16; off; off >>= 1) {
                float ov = __shfl_xor_sync(0xffffffffu, v, off);
                int   oi = __shfl_xor_sync(0xffffffffu, idx, off);
                if (ov > v || (ov == v && oi < idx)) { v = ov; idx = oi; }
            }
            float e0 = expf(L0 - v);
            float e1 = expf(L1 - v);
            float s = e0 + e1;
            #pragma unroll
            for (int off = 16; off; off >>= 1)
                s += __shfl_xor_sync(0xffffffffu, s, off);
            float inv = 1.0f / s;
            p0 += e0 * inv;
            p1 += e1 * inv;
            if (lane == 0) {
                int t = tbase + row;
                g_expert[t] = idx;
                g_gate[t]   = inv;
            }
        }
        atomicAdd(&sm.g.proxy[lane], p0);
        atomicAdd(&sm.g.proxy[lane + 32], p1);
        __syncthreads();
        if (tid < E_DIM) g_proxy_partial[b * E_DIM + tid] = sm.g.proxy[tid];

        __threadfence();
        __syncthreads();
        if (tid == 0) atomicAdd(&g_gemm_done, 1u);
    } else if (b == GEMM_BLOCKS) {
        // -------- coordinator: scan + aux, hidden under the ongoing fill --------
        int lane = tid & 31;
        unsigned lt = (1u << lane) - 1u;

        if (tid == 0) {
            while (*(volatile unsigned int*)&g_gemm_done < GEMM_BLOCKS) __nanosleep(64);
            g_gemm_done = 0;    // sole consumer; reset for next graph replay
        }
        __syncthreads();
        __threadfence();

        float auxAcc = 0.f;
        const int G = GS_TOK / S_DIM;
        for (int g = 0; g < G; g++) {
            for (int i = tid; i < 64 * E_DIM; i += 256) sm.s.hist[i] = 0;
            __syncthreads();

            #pragma unroll
            for (int i = 0; i < 8; i++) {
                int s = i * 256 + tid;
                int e = g_expert[g * S_DIM + s];
                unsigned m = __match_any_sync(0xffffffffu, e);
                int r = __popc(m & lt);
                sm.s.rank8[s] = (unsigned char)r;
                sm.s.ex8[s]   = (unsigned char)e;
                if (r == 0) sm.s.hist[(s >> 5) * E_DIM + e] = __popc(m);
            }
            __syncthreads();

            if (tid < E_DIM) {
                int run = 0;
                for (int c = 0; c < 64; c++) {
                    int v = sm.s.hist[c * E_DIM + tid];
                    sm.s.hist[c * E_DIM + tid] = run;
                    run += v;
                }
                float proxy = 0.f;
                for (int bb = 0; bb < GEMM_BLOCKS / 4; bb++)
                    proxy += g_proxy_partial[(g * (GEMM_BLOCKS / 4) + bb) * E_DIM + tid];
                const float invden = 1.0f / (2048.0f * 1.000001f);
                auxAcc += (proxy * invden) * ((float)run * invden);
            }
            __syncthreads();

            #pragma unroll
            for (int i = 0; i < 8; i++) {
                int s = i * 256 + tid;
                int e = sm.s.ex8[s];
                int pos = sm.s.hist[(s >> 5) * E_DIM + e] + (int)sm.s.rank8[s];
                g_epos[g * S_DIM + s] = (pos < C) ? (e * C + pos) : -1;
            }
            __syncthreads();
        }

        if (tid < E_DIM) sm.s.red[tid] = auxAcc;
        __syncthreads();
        if (tid < 32) {
            float v = sm.s.red[tid] + sm.s.red[tid + 32];
            #pragma unroll
            for (int off = 16; off; off >>= 1)
                v += __shfl_xor_sync(0xffffffffu, v, off);
            if (tid == 0) { g_aux = v * aux_scale; __threadfence(); }
        }
    } else {
        // -------- zero fill: contiguous chunks, 256-bit streaming stores --------
        long long n8  = out_size >> 3;               // float8 units
        long long fb  = b - GEMM_BLOCKS - 1;
        long long per = n8 / FILL_BLOCKS;
        long long rem = n8 - per * FILL_BLOCKS;
        long long base = fb * per + (fb < rem ? fb : rem);
        if (fb < rem) per++;

        float* dst = out + base * 8;
        float zf = 0.f;
        long long i = tid;
        #define STV8(p) asm volatile( \
            "st.global.cs.v8.f32 [%0], {%1,%1,%1,%1,%1,%1,%1,%1};" \
            :: "l"(p), "f"(zf) : "memory")
        for (; i + 768 < per; i += 1024) {
            STV8(dst + (i        ) * 8);
            STV8(dst + (i +  256 ) * 8);
            STV8(dst + (i +  512 ) * 8);
            STV8(dst + (i +  768 ) * 8);
        }
        for (; i < per; i += 256) STV8(dst + i * 8);
        #undef STV8

        if (fb == 0) {   // scalar tail incl. aux slot (k2 overwrites aux)
            for (long long t = n8 * 8 + tid; t < out_size; t += 256)
                out[t] = 0.f;
        }
    }
}

// ---------------------------------------------------------------------------
// K2: minimal scatter (positions precomputed by hidden coordinator)
// ---------------------------------------------------------------------------
__global__ __launch_bounds__(256)
void k2_scatter(float* __restrict__ out, long long half, long long EC,
                long long aux_idx)
{
    int t = blockIdx.x * 256 + threadIdx.x;
    if (t == 0) out[aux_idx] = g_aux;
    int ep = g_epos[t];
    if (ep >= 0) {
        long long idx = (long long)t * EC + ep;
        out[idx]        = g_gate[t];
        out[half + idx] = 1.0f;
    }
}

extern "C" void kernel_launch(void* const* d_in, const int* in_sizes, int n_in,
                              void* d_out, int out_size)
{
    const float* X = (const float*)d_in[0];
    const float* W = (const float*)d_in[1];
    float* out = (float*)d_out;

    long long osz  = (long long)out_size;
    long long half = (osz - 1) / 2;
    int GS = in_sizes[0] / M_DIM;                    // 8192
    int C  = (int)(half / ((long long)GS * E_DIM));  // 160
    int G  = GS / S_DIM;                             // 4
    float aux_scale = (float)((double)E_DIM * E_DIM * 0.01 / ((double)G * E_DIM));

    k1_gemm_fill<<<TOTAL_BLOCKS, 256>>>(X, W, out, osz, C, aux_scale);
    k2_scatter<<<GS_TOK / 256, 256>>>(out, half, (long long)E_DIM * C, osz - 1);
}

// round 10
// speedup vs baseline: 1.0370x; 1.0370x over previous
#include <cuda_runtime.h>

#define M_DIM 1024
#define E_DIM 64
#define S_DIM 2048
#define GS_TOK 8192
#define GEMM_BLOCKS 128      // 64 tokens per block; 32 blocks per group
#define FILL_BLOCKS 2048

__device__ float g_proxy_partial[GEMM_BLOCKS * E_DIM];
__device__ int   g_counts[GEMM_BLOCKS * E_DIM];
__device__ float2 g_sc[GS_TOK];          // {epos (as int bits), gate}
__device__ float g_group_loss[4];
__device__ float g_aux;
__device__ unsigned int g_grp_done[4];
__device__ unsigned int g_loss_cnt;
__device__ unsigned int g_epos_done;
__device__ unsigned int g_aux_ready;
__device__ unsigned int g_fill_done;

// ---------------------------------------------------------------------------
// Single kernel: GEMM + distributed scan (hidden) + zero-fill + last-block scatter
// ---------------------------------------------------------------------------
__global__ __launch_bounds__(256)
void k_all(const float* __restrict__ X, const float* __restrict__ W,
           float* __restrict__ out, long long out_size,
           int C, float aux_scale, long long half, long long aux_idx)
{
    __shared__ float smem[4160];   // As[64][33]=2112 + Bs[32][64]=2048; L[64][65] overlays
    __shared__ float proxyS[E_DIM];
    __shared__ int   exS[64];
    __shared__ float gateS[64];
    __shared__ int   cntS[128];    // cnt_chunk0[64], cnt_chunk1[64]
    __shared__ int   offS[64];
    __shared__ float redA[64];
    __shared__ int   flagS;

    int b = blockIdx.x;
    int tid = threadIdx.x;

    if (b < GEMM_BLOCKS) {
        // ================= GEMM: 64 tokens x 64 experts (EXACT R2 body) =========
        float* As = smem;
        float* Bs = smem + 2112;
        int tx = tid & 15, ty = tid >> 4;
        if (tid < E_DIM) proxyS[tid] = 0.f;

        unsigned long long acc2[4][2];
        #pragma unroll
        for (int i = 0; i < 4; i++) { acc2[i][0] = 0ull; acc2[i][1] = 0ull; }

        int tbase = b * 64;
        const float* Xb = X + (long long)tbase * M_DIM;

        for (int kt = 0; kt < M_DIM; kt += 32) {
            #pragma unroll
            for (int j = 0; j < 2; j++) {
                int t  = (tid >> 3) + j * 32;
                int kq = tid & 7;
                float4 v = *(const float4*)(Xb + (long long)t * M_DIM + kt + kq * 4);
                float* dst = As + t * 33 + kq * 4;
                dst[0] = v.x; dst[1] = v.y; dst[2] = v.z; dst[3] = v.w;
            }
            #pragma unroll
            for (int j = 0; j < 2; j++) {
                int idx = tid + j * 256;
                int r = idx >> 4, c4 = idx & 15;
                ((float4*)Bs)[r * 16 + c4] = ((const float4*)(W + (long long)(kt + r) * E_DIM))[c4];
            }
            __syncthreads();
            #pragma unroll
            for (int kk = 0; kk < 32; kk++) {
                ulonglong2 bq = *((const ulonglong2*)(Bs + kk * 64) + tx);
                #pragma unroll
                for (int i = 0; i < 4; i++) {
                    float a = As[(ty * 4 + i) * 33 + kk];
                    unsigned long long ap;
                    asm("mov.b64 %0, {%1, %1};" : "=l"(ap) : "f"(a));
                    asm("fma.rn.f32x2 %0, %1, %2, %0;" : "+l"(acc2[i][0]) : "l"(ap), "l"(bq.x));
                    asm("fma.rn.f32x2 %0, %1, %2, %0;" : "+l"(acc2[i][1]) : "l"(ap), "l"(bq.y));
                }
            }
            __syncthreads();
        }

        float* L = smem;   // [64][65]
        #pragma unroll
        for (int i = 0; i < 4; i++) {
            float2 v0 = *reinterpret_cast<float2*>(&acc2[i][0]);
            float2 v1 = *reinterpret_cast<float2*>(&acc2[i][1]);
            float* row = L + (ty * 4 + i) * 65 + tx * 4;
            row[0] = v0.x; row[1] = v0.y; row[2] = v1.x; row[3] = v1.y;
        }
        __syncthreads();

        int w = tid >> 5, lane = tid & 31;
        float p0 = 0.f, p1 = 0.f;
        #pragma unroll
        for (int i = 0; i < 8; i++) {
            int row = w * 8 + i;
            float L0 = L[row * 65 + lane];
            float L1 = L[row * 65 + lane + 32];
            float v; int idx;
            if (L0 >= L1) { v = L0; idx = lane; } else { v = L1; idx = lane + 32; }
            #pragma unroll
            for (int off = 16; off; off >>= 1) {
                float ov = __shfl_xor_sync(0xffffffffu, v, off);
                int   oi = __shfl_xor_sync(0xffffffffu, idx, off);
                if (ov > v || (ov == v && oi < idx)) { v = ov; idx = oi; }
            }
            float e0 = expf(L0 - v);
            float e1 = expf(L1 - v);
            float s = e0 + e1;
            #pragma unroll
            for (int off = 16; off; off >>= 1)
                s += __shfl_xor_sync(0xffffffffu, s, off);
            float inv = 1.0f / s;
            p0 += e0 * inv;
            p1 += e1 * inv;
            if (lane == 0) { exS[row] = idx; gateS[row] = inv; }
        }
        atomicAdd(&proxyS[lane], p0);
        atomicAdd(&proxyS[lane + 32], p1);
        __syncthreads();

        // ================= distributed scan (hidden under fill) =================
        int g  = b >> 5;        // group (32 blocks per group)
        int lb = b & 31;        // local block index within group

        if (tid < 128) cntS[tid] = 0;
        __syncthreads();

        int myexp = 0, myrank = 0;
        if (tid < 64) {   // warps 0,1 fully active; token = tbase + tid
            myexp = exS[tid];
            unsigned m = __match_any_sync(0xffffffffu, myexp);
            myrank = __popc(m & ((1u << lane) - 1u));
            if (myrank == 0) cntS[(tid >> 5) * 64 + myexp] = __popc(m);
        }
        __syncthreads();
        if (tid < 64) {
            if (tid >= 32) myrank += cntS[myexp];               // add chunk-0 count
            g_counts[b * E_DIM + tid] = cntS[tid] + cntS[64 + tid];
            g_proxy_partial[b * E_DIM + tid] = proxyS[tid];
        }
        __threadfence();
        __syncthreads();
        if (tid == 0) {
            atomicAdd(&g_grp_done[g], 1u);
            while (*(volatile unsigned int*)&g_grp_done[g] < 32u) __nanosleep(64);
        }
        __syncthreads();
        __threadfence();

        // exclusive offsets: sum counts of earlier blocks in this group
        if (tid < 64) {
            int off = 0;
            #pragma unroll 4
            for (int bb = 0; bb < lb; bb++)
                off += g_counts[(g * 32 + bb) * E_DIM + tid];
            offS[tid] = off;
        }
        __syncthreads();

        if (tid < 64) {
            int pos = offS[myexp] + myrank;
            int ep = (pos < C) ? (myexp * C + pos) : -1;
            g_sc[tbase + tid] = make_float2(__int_as_float(ep), gateS[tid]);
        }
        __threadfence();
        __syncthreads();
        if (tid == 0) atomicAdd(&g_epos_done, 1u);

        // group leader (lb==31): per-group aux loss
        if (lb == 31) {
            if (tid < 64) {
                float proxy = 0.f;
                #pragma unroll 4
                for (int bb = 0; bb < 32; bb++)
                    proxy += g_proxy_partial[(g * 32 + bb) * E_DIM + tid];
                int run = offS[tid] + cntS[tid] + cntS[64 + tid];
                const float invden = 1.0f / (2048.0f * 1.000001f);
                redA[tid] = (proxy * invden) * ((float)run * invden);
            }
            __syncthreads();
            if (tid < 32) {
                float v = redA[tid] + redA[tid + 32];
                #pragma unroll
                for (int off = 16; off; off >>= 1)
                    v += __shfl_xor_sync(0xffffffffu, v, off);
                if (tid == 0) {
                    g_group_loss[g] = v;
                    __threadfence();
                    unsigned p = atomicAdd(&g_loss_cnt, 1u);
                    if (p == 3u) {
                        __threadfence();
                        float a = 0.f;
                        for (int gg = 0; gg < 4; gg++) a += g_group_loss[gg];
                        g_aux = a * aux_scale;
                        g_loss_cnt = 0;
                        __threadfence();
                        g_aux_ready = 1;
                    }
                }
            }
        }
    } else {
        // ================= zero fill (EXACT R2 body) + last-block scatter ========
        long long n4  = out_size >> 2;
        long long fb  = b - GEMM_BLOCKS;
        long long per = n4 / FILL_BLOCKS;
        long long rem = n4 - per * FILL_BLOCKS;
        long long base = fb * per + (fb < rem ? fb : rem);
        if (fb < rem) per++;

        float4 z = make_float4(0.f, 0.f, 0.f, 0.f);
        float4* dst = (float4*)out + base;
        long long i = tid;
        for (; i + 768 < per; i += 1024) {
            __stcs(dst + i,       z);
            __stcs(dst + i + 256, z);
            __stcs(dst + i + 512, z);
            __stcs(dst + i + 768, z);
        }
        for (; i < per; i += 256) __stcs(dst + i, z);

        if (fb == 0) {   // scalar tail incl. aux slot (scatter overwrites aux later)
            for (long long t = n4 * 4 + tid; t < out_size; t += 256)
                out[t] = 0.f;
        }

        __threadfence();
        __syncthreads();
        if (tid == 0) {
            unsigned p = atomicAdd(&g_fill_done, 1u);
            flagS = (p == FILL_BLOCKS - 1u) ? 1 : 0;
        }
        __syncthreads();

        if (flagS) {
            // this is the last fill block to finish: all zeros are done
            if (tid == 0) {
                while (*(volatile unsigned int*)&g_epos_done < GEMM_BLOCKS) __nanosleep(64);
                while (*(volatile unsigned int*)&g_aux_ready == 0u) __nanosleep(64);
            }
            __syncthreads();
            __threadfence();

            long long EC = (long long)E_DIM * C;
            #pragma unroll
            for (int it = 0; it < GS_TOK / 256; it++) {
                int t = it * 256 + tid;
                float2 sc = g_sc[t];
                int ep = __float_as_int(sc.x);
                if (ep >= 0) {
                    long long idx = (long long)t * EC + ep;
                    out[idx]        = sc.y;
                    out[half + idx] = 1.0f;
                }
            }
            if (tid == 0) out[aux_idx] = g_aux;

            __syncthreads();
            if (tid == 0) {   // last actor: reset for next graph replay
                g_fill_done = 0;
                g_epos_done = 0;
                g_aux_ready = 0;
                g_grp_done[0] = 0; g_grp_done[1] = 0;
                g_grp_done[2] = 0; g_grp_done[3] = 0;
                __threadfence();
            }
        }
    }
}

extern "C" void kernel_launch(void* const* d_in, const int* in_sizes, int n_in,
                              void* d_out, int out_size)
{
    const float* X = (const float*)d_in[0];
    const float* W = (const float*)d_in[1];
    float* out = (float*)d_out;

    long long osz  = (long long)out_size;
    long long half = (osz - 1) / 2;
    int GS = in_sizes[0] / M_DIM;                    // 8192
    int C  = (int)(half / ((long long)GS * E_DIM));  // 160
    int G  = GS / S_DIM;                             // 4
    float aux_scale = (float)((double)E_DIM * E_DIM * 0.01 / ((double)G * E_DIM));

    k_all<<<GEMM_BLOCKS + FILL_BLOCKS, 256>>>(X, W, out, osz, C, aux_scale,
                                              half, osz - 1);
}

// round 11
// speedup vs baseline: 1.0748x; 1.0365x over previous
#include <cuda_runtime.h>

#define M_DIM 1024
#define E_DIM 64
#define S_DIM 2048
#define GS_TOK 8192
#define GEMM_BLOCKS 128      // 64 tokens per block

__device__ float g_proxy_partial[GEMM_BLOCKS * E_DIM];
__device__ int   g_expert[GS_TOK];
__device__ float g_gate[GS_TOK];
__device__ float g_group_loss[8];
__device__ unsigned int g_loss_cnt;

// ---------------------------------------------------------------------------
// K1: gating GEMM only (f32x2 packed FFMA) — fill handled by driver memset
// ---------------------------------------------------------------------------
__global__ __launch_bounds__(256)
void k1_gemm(const float* __restrict__ X, const float* __restrict__ W)
{
    __shared__ float smem[4160];   // As[64][33]=2112 + Bs[32][64]=2048; L[64][65] overlays
    __shared__ float proxyS[E_DIM];

    int b = blockIdx.x;
    int tid = threadIdx.x;
    if (b == 0 && tid == 0) g_loss_cnt = 0;   // reset for this replay

    float* As = smem;
    float* Bs = smem + 2112;
    int tx = tid & 15, ty = tid >> 4;
    if (tid < E_DIM) proxyS[tid] = 0.f;

    unsigned long long acc2[4][2];
    #pragma unroll
    for (int i = 0; i < 4; i++) { acc2[i][0] = 0ull; acc2[i][1] = 0ull; }

    int tbase = b * 64;
    const float* Xb = X + (long long)tbase * M_DIM;

    for (int kt = 0; kt < M_DIM; kt += 32) {
        #pragma unroll
        for (int j = 0; j < 2; j++) {
            int t  = (tid >> 3) + j * 32;
            int kq = tid & 7;
            float4 v = *(const float4*)(Xb + (long long)t * M_DIM + kt + kq * 4);
            float* dst = As + t * 33 + kq * 4;
            dst[0] = v.x; dst[1] = v.y; dst[2] = v.z; dst[3] = v.w;
        }
        #pragma unroll
        for (int j = 0; j < 2; j++) {
            int idx = tid + j * 256;
            int r = idx >> 4, c4 = idx & 15;
            ((float4*)Bs)[r * 16 + c4] = ((const float4*)(W + (long long)(kt + r) * E_DIM))[c4];
        }
        __syncthreads();
        #pragma unroll
        for (int kk = 0; kk < 32; kk++) {
            ulonglong2 bq = *((const ulonglong2*)(Bs + kk * 64) + tx);
            #pragma unroll
            for (int i = 0; i < 4; i++) {
                float a = As[(ty * 4 + i) * 33 + kk];
                unsigned long long ap;
                asm("mov.b64 %0, {%1, %1};" : "=l"(ap) : "f"(a));
                asm("fma.rn.f32x2 %0, %1, %2, %0;" : "+l"(acc2[i][0]) : "l"(ap), "l"(bq.x));
                asm("fma.rn.f32x2 %0, %1, %2, %0;" : "+l"(acc2[i][1]) : "l"(ap), "l"(bq.y));
            }
        }
        __syncthreads();
    }

    float* L = smem;   // [64][65]
    #pragma unroll
    for (int i = 0; i < 4; i++) {
        float2 v0 = *reinterpret_cast<float2*>(&acc2[i][0]);
        float2 v1 = *reinterpret_cast<float2*>(&acc2[i][1]);
        float* row = L + (ty * 4 + i) * 65 + tx * 4;
        row[0] = v0.x; row[1] = v0.y; row[2] = v1.x; row[3] = v1.y;
    }
    __syncthreads();

    int w = tid >> 5, lane = tid & 31;
    float p0 = 0.f, p1 = 0.f;
    #pragma unroll
    for (int i = 0; i < 8; i++) {
        int row = w * 8 + i;
        float L0 = L[row * 65 + lane];
        float L1 = L[row * 65 + lane + 32];
        float v; int idx;
        if (L0 >= L1) { v = L0; idx = lane; } else { v = L1; idx = lane + 32; }
        #pragma unroll
        for (int off = 16; off; off >>= 1) {
            float ov = __shfl_xor_sync(0xffffffffu, v, off);
            int   oi = __shfl_xor_sync(0xffffffffu, idx, off);
            if (ov > v || (ov == v && oi < idx)) { v = ov; idx = oi; }
        }
        float e0 = expf(L0 - v);
        float e1 = expf(L1 - v);
        float s = e0 + e1;
        #pragma unroll
        for (int off = 16; off; off >>= 1)
            s += __shfl_xor_sync(0xffffffffu, s, off);
        float inv = 1.0f / s;
        p0 += e0 * inv;
        p1 += e1 * inv;
        if (lane == 0) {
            int t = tbase + row;
            g_expert[t] = idx;
            g_gate[t]   = inv;
        }
    }
    atomicAdd(&proxyS[lane], p0);
    atomicAdd(&proxyS[lane + 32], p1);
    __syncthreads();
    if (tid < E_DIM) g_proxy_partial[b * E_DIM + tid] = proxyS[tid];
}

// ---------------------------------------------------------------------------
// K2: position-in-expert scan + capacity drop + direct scatter + aux (R2 body)
// ---------------------------------------------------------------------------
__global__ __launch_bounds__(1024)
void k2_scan_scatter(float* __restrict__ out, long long half, int C,
                     long long aux_idx, float aux_scale, int G)
{
    __shared__ int hist[64 * E_DIM];
    __shared__ unsigned char rank8[S_DIM];
    __shared__ unsigned char ex8[S_DIM];
    __shared__ float redS[E_DIM];

    int g = blockIdx.x;
    int tid = threadIdx.x;
    for (int i = tid; i < 64 * E_DIM; i += 1024) hist[i] = 0;
    __syncthreads();

    int lane = tid & 31;
    unsigned lt = (1u << lane) - 1u;

    #pragma unroll
    for (int h = 0; h < 2; h++) {
        int s = h * 1024 + tid;
        int e = g_expert[g * S_DIM + s];
        unsigned m = __match_any_sync(0xffffffffu, e);
        int r = __popc(m & lt);
        rank8[s] = (unsigned char)r;
        ex8[s]   = (unsigned char)e;
        if (r == 0) hist[(s >> 5) * E_DIM + e] = __popc(m);
    }
    __syncthreads();

    if (tid < E_DIM) {
        int run = 0;
        for (int c = 0; c < 64; c++) {
            int v = hist[c * E_DIM + tid];
            hist[c * E_DIM + tid] = run;
            run += v;
        }
        float proxy = 0.f;
        for (int bb = 0; bb < GEMM_BLOCKS / 4; bb++)
            proxy += g_proxy_partial[(g * (GEMM_BLOCKS / 4) + bb) * E_DIM + tid];
        const float invden = 1.0f / (2048.0f * 1.000001f);
        redS[tid] = (proxy * invden) * ((float)run * invden);
    }
    __syncthreads();
    if (tid < 32) {
        float v = redS[tid] + redS[tid + 32];
        #pragma unroll
        for (int off = 16; off; off >>= 1)
            v += __shfl_xor_sync(0xffffffffu, v, off);
        if (tid == 0) {
            g_group_loss[g] = v;
            __threadfence();
            atomicAdd(&g_loss_cnt, 1u);
        }
    }

    if (g == 0 && tid == 0) {
        while (atomicAdd(&g_loss_cnt, 0u) < (unsigned)G) { }
        float a = 0.f;
        for (int gg = 0; gg < G; gg++) a += g_group_loss[gg];
        out[aux_idx] = a * aux_scale;
    }
    __syncthreads();

    #pragma unroll
    for (int h = 0; h < 2; h++) {
        int s = h * 1024 + tid;
        int e = ex8[s];
        int pos = hist[(s >> 5) * E_DIM + e] + (int)rank8[s];
        int t = g * S_DIM + s;
        if (pos < C) {
            float v = g_gate[t];
            long long idx = ((long long)t * E_DIM + e) * C + pos;
            out[idx]        = v;
            out[half + idx] = 1.0f;
        }
    }
}

extern "C" void kernel_launch(void* const* d_in, const int* in_sizes, int n_in,
                              void* d_out, int out_size)
{
    const float* X = (const float*)d_in[0];
    const float* W = (const float*)d_in[1];
    float* out = (float*)d_out;

    long long osz  = (long long)out_size;
    long long half = (osz - 1) / 2;
    int GS = in_sizes[0] / M_DIM;                    // 8192
    int C  = (int)(half / ((long long)GS * E_DIM));  // 160
    int G  = GS / S_DIM;                             // 4
    float aux_scale = (float)((double)E_DIM * E_DIM * 0.01 / ((double)G * E_DIM));

    static cudaStream_t sB = nullptr;
    static cudaEvent_t evFork = nullptr, evJoin = nullptr;
    if (sB == nullptr) {
        cudaStreamCreateWithFlags(&sB, cudaStreamNonBlocking);
        cudaEventCreateWithFlags(&evFork, cudaEventDisableTiming);
        cudaEventCreateWithFlags(&evJoin, cudaEventDisableTiming);
    }

    // GEMM first (its 128 blocks grab SM slots before the memset grid saturates)
    k1_gemm<<<GEMM_BLOCKS, 256>>>(X, W);

    // driver memset on a forked stream — independent graph node, runs concurrently
    cudaEventRecord(evFork, 0);
    cudaStreamWaitEvent(sB, evFork, 0);
    cudaMemsetAsync(out, 0, (size_t)osz * sizeof(float), sB);
    cudaEventRecord(evJoin, sB);
    cudaStreamWaitEvent(0, evJoin, 0);

    // scan + scatter after both GEMM and memset complete
    k2_scan_scatter<<<G, 1024>>>(out, half, C, osz - 1, aux_scale, G);
}

// round 12
// speedup vs baseline: 1.0893x; 1.0135x over previous
#include <cuda_runtime.h>

#define M_DIM 1024
#define E_DIM 64
#define S_DIM 2048
#define GS_TOK 8192
#define GEMM_BLOCKS 128      // 64 tokens per block; 32 blocks per group
#define FILL_BLOCKS 2048

__device__ float g_proxy_partial[GEMM_BLOCKS * E_DIM];
__device__ int   g_counts[GEMM_BLOCKS * E_DIM];
__device__ float2 g_sc[GS_TOK];          // {epos (int bits), gate}
__device__ float g_group_loss[4];
__device__ float g_aux;
__device__ unsigned int g_grp_done[4];
__device__ unsigned int g_loss_cnt;

// ---------------------------------------------------------------------------
// K1: GEMM blocks (GEMM + hidden distributed scan) + fill blocks (EXACT R2)
// ---------------------------------------------------------------------------
__global__ __launch_bounds__(256)
void k1_gemm_fill(const float* __restrict__ X, const float* __restrict__ W,
                  float* __restrict__ out, long long out_size,
                  int C, float aux_scale)
{
    __shared__ float smem[4160];   // As[64][33]=2112 + Bs[32][64]=2048; L[64][65] overlays
    __shared__ float proxyS[E_DIM];
    __shared__ int   exS[64];
    __shared__ float gateS[64];
    __shared__ int   cntS[128];    // per-32-token-chunk counts
    __shared__ int   offS[64];
    __shared__ float redA[64];

    int b = blockIdx.x;
    int tid = threadIdx.x;

    if (b < GEMM_BLOCKS) {
        // ================= GEMM: 64 tokens x 64 experts (EXACT R2 body) =========
        float* As = smem;
        float* Bs = smem + 2112;
        int tx = tid & 15, ty = tid >> 4;
        if (tid < E_DIM) proxyS[tid] = 0.f;

        unsigned long long acc2[4][2];
        #pragma unroll
        for (int i = 0; i < 4; i++) { acc2[i][0] = 0ull; acc2[i][1] = 0ull; }

        int tbase = b * 64;
        const float* Xb = X + (long long)tbase * M_DIM;

        for (int kt = 0; kt < M_DIM; kt += 32) {
            #pragma unroll
            for (int j = 0; j < 2; j++) {
                int t  = (tid >> 3) + j * 32;
                int kq = tid & 7;
                float4 v = *(const float4*)(Xb + (long long)t * M_DIM + kt + kq * 4);
                float* dst = As + t * 33 + kq * 4;
                dst[0] = v.x; dst[1] = v.y; dst[2] = v.z; dst[3] = v.w;
            }
            #pragma unroll
            for (int j = 0; j < 2; j++) {
                int idx = tid + j * 256;
                int r = idx >> 4, c4 = idx & 15;
                ((float4*)Bs)[r * 16 + c4] = ((const float4*)(W + (long long)(kt + r) * E_DIM))[c4];
            }
            __syncthreads();
            #pragma unroll
            for (int kk = 0; kk < 32; kk++) {
                ulonglong2 bq = *((const ulonglong2*)(Bs + kk * 64) + tx);
                #pragma unroll
                for (int i = 0; i < 4; i++) {
                    float a = As[(ty * 4 + i) * 33 + kk];
                    unsigned long long ap;
                    asm("mov.b64 %0, {%1, %1};" : "=l"(ap) : "f"(a));
                    asm("fma.rn.f32x2 %0, %1, %2, %0;" : "+l"(acc2[i][0]) : "l"(ap), "l"(bq.x));
                    asm("fma.rn.f32x2 %0, %1, %2, %0;" : "+l"(acc2[i][1]) : "l"(ap), "l"(bq.y));
                }
            }
            __syncthreads();
        }

        float* L = smem;   // [64][65]
        #pragma unroll
        for (int i = 0; i < 4; i++) {
            float2 v0 = *reinterpret_cast<float2*>(&acc2[i][0]);
            float2 v1 = *reinterpret_cast<float2*>(&acc2[i][1]);
            float* row = L + (ty * 4 + i) * 65 + tx * 4;
            row[0] = v0.x; row[1] = v0.y; row[2] = v1.x; row[3] = v1.y;
        }
        __syncthreads();

        int w = tid >> 5, lane = tid & 31;
        float p0 = 0.f, p1 = 0.f;
        #pragma unroll
        for (int i = 0; i < 8; i++) {
            int row = w * 8 + i;
            float L0 = L[row * 65 + lane];
            float L1 = L[row * 65 + lane + 32];
            float v; int idx;
            if (L0 >= L1) { v = L0; idx = lane; } else { v = L1; idx = lane + 32; }
            #pragma unroll
            for (int off = 16; off; off >>= 1) {
                float ov = __shfl_xor_sync(0xffffffffu, v, off);
                int   oi = __shfl_xor_sync(0xffffffffu, idx, off);
                if (ov > v || (ov == v && oi < idx)) { v = ov; idx = oi; }
            }
            float e0 = expf(L0 - v);
            float e1 = expf(L1 - v);
            float s = e0 + e1;
            #pragma unroll
            for (int off = 16; off; off >>= 1)
                s += __shfl_xor_sync(0xffffffffu, s, off);
            float inv = 1.0f / s;
            p0 += e0 * inv;
            p1 += e1 * inv;
            if (lane == 0) { exS[row] = idx; gateS[row] = inv; }
        }
        atomicAdd(&proxyS[lane], p0);
        atomicAdd(&proxyS[lane + 32], p1);
        __syncthreads();

        // ======== distributed scan across the 32 co-resident blocks of group ====
        int g  = b >> 5;        // group
        int lb = b & 31;        // local block index within group

        if (tid < 128) cntS[tid] = 0;
        __syncthreads();

        int myexp = 0, myrank = 0;
        if (tid < 64) {   // warps 0,1 fully active; token = tbase + tid
            myexp = exS[tid];
            unsigned m = __match_any_sync(0xffffffffu, myexp);
            myrank = __popc(m & ((1u << lane) - 1u));
            if (myrank == 0) cntS[(tid >> 5) * 64 + myexp] = __popc(m);
        }
        __syncthreads();
        if (tid < 64) {
            if (tid >= 32) myrank += cntS[myexp];    // add chunk-0 count
            g_counts[b * E_DIM + tid] = cntS[tid] + cntS[64 + tid];
            g_proxy_partial[b * E_DIM + tid] = proxyS[tid];
        }
        __threadfence();
        __syncthreads();
        if (tid == 0) {
            atomicAdd(&g_grp_done[g], 1u);
            while (*(volatile unsigned int*)&g_grp_done[g] < 32u) __nanosleep(64);
        }
        __syncthreads();
        __threadfence();

        // exclusive offsets: sum counts of earlier blocks in this group
        if (tid < 64) {
            int off = 0;
            #pragma unroll 4
            for (int bb = 0; bb < lb; bb++)
                off += g_counts[(g * 32 + bb) * E_DIM + tid];
            offS[tid] = off;
        }
        __syncthreads();

        if (tid < 64) {
            int pos = offS[myexp] + myrank;
            int ep = (pos < C) ? (myexp * C + pos) : -1;
            g_sc[tbase + tid] = make_float2(__int_as_float(ep), gateS[tid]);
        }

        // group leader (lb==31): per-group aux; global finalizer on the 4th
        if (lb == 31) {
            if (tid < 64) {
                float proxy = 0.f;
                #pragma unroll 4
                for (int bb = 0; bb < 32; bb++)
                    proxy += g_proxy_partial[(g * 32 + bb) * E_DIM + tid];
                int run = offS[tid] + cntS[tid] + cntS[64 + tid];
                const float invden = 1.0f / (2048.0f * 1.000001f);
                redA[tid] = (proxy * invden) * ((float)run * invden);
            }
            __syncthreads();
            if (tid < 32) {
                float v = redA[tid] + redA[tid + 32];
                #pragma unroll
                for (int off = 16; off; off >>= 1)
                    v += __shfl_xor_sync(0xffffffffu, v, off);
                if (tid == 0) {
                    g_group_loss[g] = v;
                    __threadfence();
                    unsigned p = atomicAdd(&g_loss_cnt, 1u);
                    if (p == 3u) {                 // last group leader finalizes
                        __threadfence();
                        float a = 0.f;
                        for (int gg = 0; gg < 4; gg++) a += g_group_loss[gg];
                        g_aux = a * aux_scale;
                        g_loss_cnt = 0;            // reset for next replay
                        __threadfence();
                    }
                }
            }
        }
    } else {
        // ================= zero fill: EXACT R2 body, no additions ================
        long long n4  = out_size >> 2;
        long long fb  = b - GEMM_BLOCKS;
        long long per = n4 / FILL_BLOCKS;
        long long rem = n4 - per * FILL_BLOCKS;
        long long base = fb * per + (fb < rem ? fb : rem);
        if (fb < rem) per++;

        float4 z = make_float4(0.f, 0.f, 0.f, 0.f);
        float4* dst = (float4*)out + base;
        long long i = tid;
        for (; i + 768 < per; i += 1024) {
            __stcs(dst + i,       z);
            __stcs(dst + i + 256, z);
            __stcs(dst + i + 512, z);
            __stcs(dst + i + 768, z);
        }
        for (; i < per; i += 256) __stcs(dst + i, z);

        if (fb == 0) {   // scalar tail incl. aux slot (k2 overwrites aux)
            for (long long t = n4 * 4 + tid; t < out_size; t += 256)
                out[t] = 0.f;
        }
    }
}

// ---------------------------------------------------------------------------
// K2: minimal scatter (8us floor) + aux + counter reset
// ---------------------------------------------------------------------------
__global__ __launch_bounds__(256)
void k2_scatter(float* __restrict__ out, long long half, long long EC,
                long long aux_idx)
{
    int t = blockIdx.x * 256 + threadIdx.x;
    if (t == 0) {
        out[aux_idx] = g_aux;
        g_grp_done[0] = 0; g_grp_done[1] = 0;    // safe: k1 fully retired
        g_grp_done[2] = 0; g_grp_done[3] = 0;
    }
    float2 sc = g_sc[t];
    int ep = __float_as_int(sc.x);
    if (ep >= 0) {
        long long idx = (long long)t * EC + ep;
        out[idx]        = sc.y;
        out[half + idx] = 1.0f;
    }
}

extern "C" void kernel_launch(void* const* d_in, const int* in_sizes, int n_in,
                              void* d_out, int out_size)
{
    const float* X = (const float*)d_in[0];
    const float* W = (const float*)d_in[1];
    float* out = (float*)d_out;

    long long osz  = (long long)out_size;
    long long half = (osz - 1) / 2;
    int GS = in_sizes[0] / M_DIM;                    // 8192
    int C  = (int)(half / ((long long)GS * E_DIM));  // 160
    int G  = GS / S_DIM;                             // 4
    float aux_scale = (float)((double)E_DIM * E_DIM * 0.01 / ((double)G * E_DIM));

    k1_gemm_fill<<<GEMM_BLOCKS + FILL_BLOCKS, 256>>>(X, W, out, osz, C, aux_scale);
    k2_scatter<<<GS_TOK / 256, 256>>>(out, half, (long long)E_DIM * C, osz - 1);
}